// round 5
// baseline (speedup 1.0000x reference)
#include <cuda_runtime.h>
#include <math.h>

// ---------------- scratch (device globals; no allocations) ----------------
#define NB 16
__device__ float g_h1[NB*64*256*256];
__device__ float g_h2[NB*128*128*128];
__device__ float g_h3[NB*256*64*64];
__device__ float g_z [NB*512*32*32];
__device__ float g_zf[NB*1024*512];
__device__ float g_zq[NB*512*32*32];
__device__ float g_g1[NB*256*64*64];
__device__ float g_g2[NB*128*128*128];
__device__ float g_g3[NB*64*256*256];
__device__ float g_cn[8192];
__device__ int   g_idx[16384];

// ---------------- stride-1 3x3 conv (conv1), 8-wide, TC=8 ----------------
template<int STRIDE, int ACT>
__global__ void __launch_bounds__(128) conv8s_k(
    const float* __restrict__ in, const float* __restrict__ wgt,
    const float* __restrict__ bias, float* __restrict__ out,
    int Cin, int Cout, int Hin, int Win, int Hout, int Wout)
{
    constexpr int CICH = 32;
    constexpr int TC = 8;
    constexpr int NW = (STRIDE == 1) ? 10 : 17;
    __shared__ float wsf[CICH * TC * 12];

    const int tid  = threadIdx.x;
    const int W8   = Wout >> 3;
    const int rows = 128 / W8;
    const int q    = tid % W8;
    const int oy   = blockIdx.y * rows + tid / W8;
    const int ox0  = q * 8;
    const int ocg  = blockIdx.x * TC;
    const int n    = blockIdx.z;

    float acc[TC][8];
#pragma unroll
    for (int o = 0; o < TC; o++)
#pragma unroll
        for (int j = 0; j < 8; j++) acc[o][j] = 0.f;

    bool rval[3]; int iyo[3];
#pragma unroll
    for (int ky = 0; ky < 3; ky++) {
        int iy = oy * STRIDE + ky - 1;
        rval[ky] = (iy >= 0 && iy < Hin);
        iyo[ky] = iy < 0 ? 0 : (iy >= Hin ? Hin - 1 : iy);
    }

    auto loadRow = [&](float (&w)[NW], int cabs, int ky) {
        const float* rp = in + ((size_t)(n * Cin + cabs) * Hin + iyo[ky]) * Win;
        if (STRIDE == 1) {
            float4 a = *(const float4*)(rp + ox0);
            float4 b = *(const float4*)(rp + ox0 + 4);
            float lft = __shfl_up_sync(0xffffffffu, b.w, 1);
            float rgt = __shfl_down_sync(0xffffffffu, a.x, 1);
            if (q == 0) lft = 0.f;
            if (q == W8 - 1) rgt = 0.f;
            w[0]=lft; w[1]=a.x; w[2]=a.y; w[3]=a.z; w[4]=a.w;
            w[5]=b.x; w[6]=b.y; w[7]=b.z; w[8]=b.w; w[9]=rgt;
        } else {
            const int ib = ox0 * 2;
            float4 a = *(const float4*)(rp + ib);
            float4 b = *(const float4*)(rp + ib + 4);
            float4 c = *(const float4*)(rp + ib + 8);
            float4 d = *(const float4*)(rp + ib + 12);
            float lft = __shfl_up_sync(0xffffffffu, d.w, 1);
            if (q == 0) lft = 0.f;
            w[0]=lft;
            w[1]=a.x; w[2]=a.y; w[3]=a.z; w[4]=a.w;
            w[5]=b.x; w[6]=b.y; w[7]=b.z; w[8]=b.w;
            w[9]=c.x; w[10]=c.y; w[11]=c.z; w[12]=c.w;
            w[13]=d.x; w[14]=d.y; w[15]=d.z; w[16]=d.w;
        }
        if (!rval[ky]) {
#pragma unroll
            for (int i = 0; i < NW; i++) w[i] = 0.f;
        }
    };

    auto computeRow = [&](float (&w)[NW], int ci, int ky) {
#pragma unroll
        for (int oc = 0; oc < TC; oc++) {
            const float4 wv = *(const float4*)(wsf + (ci * TC + oc) * 12 + ky * 4);
#pragma unroll
            for (int j = 0; j < 8; j++) {
                float a = acc[oc][j];
                a = fmaf(w[j * STRIDE + 0], wv.x, a);
                a = fmaf(w[j * STRIDE + 1], wv.y, a);
                a = fmaf(w[j * STRIDE + 2], wv.z, a);
                acc[oc][j] = a;
            }
        }
    };

    float bufA[NW], bufB[NW];
    for (int cc = 0; cc < Cin; cc += CICH) {
        const int chunk = min(CICH, Cin - cc);
        __syncthreads();
        for (int i = tid; i < chunk * TC * 9; i += 128) {
            int ci = i / (TC * 9);
            int r  = i - ci * (TC * 9);
            int oc = r / 9;
            int k  = r - oc * 9;
            wsf[(ci * TC + oc) * 12 + (k / 3) * 4 + (k % 3)] =
                wgt[(size_t)(ocg + oc) * Cin * 9 + (size_t)(cc + ci) * 9 + k];
        }
        __syncthreads();
        const int total = chunk * 3;
        loadRow(bufA, cc, 0);
        for (int m = 0; m < total; m++) {
            const int mn = m + 1;
            if (m & 1) {
                if (mn < total) loadRow(bufA, cc + mn / 3, mn % 3);
                computeRow(bufB, m / 3, m % 3);
            } else {
                if (mn < total) loadRow(bufB, cc + mn / 3, mn % 3);
                computeRow(bufA, m / 3, m % 3);
            }
        }
    }

#pragma unroll
    for (int oc = 0; oc < TC; oc++) {
        float bv = bias[ocg + oc];
        float* op = out + (((size_t)n * Cout + ocg + oc) * Hout + oy) * Wout + ox0;
        float v[8];
#pragma unroll
        for (int j = 0; j < 8; j++) {
            float a = acc[oc][j] + bv;
            if (ACT == 1) a = a > 0.f ? a : 0.f;
            v[j] = a;
        }
        *(float4*)(op)     = make_float4(v[0], v[1], v[2], v[3]);
        *(float4*)(op + 4) = make_float4(v[4], v[5], v[6], v[7]);
    }
}

// ---------------- stride-2 3x3 conv, 2 output rows x 8 wide, TC=4 -------------
// Per ci: 5 input rows feed 2 output rows; weight LDS amortized over both rows.
template<int ACT>
__global__ void convV_k(
    const float* __restrict__ in, const float* __restrict__ wgt,
    const float* __restrict__ bias, float* __restrict__ out,
    int Cin, int Cout, int Hin, int Win, int Hout, int Wout)
{
    constexpr int CICH = 32;
    constexpr int TC = 4;
    __shared__ float wsf[CICH * TC * 12];  // [ci][oc][ky*4], 6KB

    const int tid  = threadIdx.x;
    const int nthr = blockDim.x;
    const int W8   = Wout >> 3;
    const int rpb  = nthr / W8;            // row-pairs per block
    const int q    = tid % W8;
    const int rp   = blockIdx.y * rpb + tid / W8;
    const int oy0  = rp * 2;
    const int ox0  = q * 8;
    const int ocg  = blockIdx.x * TC;
    const int n    = blockIdx.z;

    float acc[2][TC][8];
#pragma unroll
    for (int ar = 0; ar < 2; ar++)
#pragma unroll
        for (int o = 0; o < TC; o++)
#pragma unroll
            for (int j = 0; j < 8; j++) acc[ar][o][j] = 0.f;

    // input rows iy = 4*rp - 1 + t, t = 0..4
    auto loadRowT = [&](float (&w)[17], int cabs, int t) {
        int yy = 4 * rp - 1 + t;
        bool rv = (yy >= 0 && yy < Hin);
        int yc = yy < 0 ? 0 : (yy >= Hin ? Hin - 1 : yy);
        const float* rpt = in + ((size_t)(n * Cin + cabs) * Hin + yc) * Win;
        const int ib = ox0 * 2;
        float4 a = *(const float4*)(rpt + ib);
        float4 b = *(const float4*)(rpt + ib + 4);
        float4 c = *(const float4*)(rpt + ib + 8);
        float4 d = *(const float4*)(rpt + ib + 12);
        float lft = __shfl_up_sync(0xffffffffu, d.w, 1);
        if (q == 0) lft = 0.f;
        w[0]=lft;
        w[1]=a.x; w[2]=a.y; w[3]=a.z; w[4]=a.w;
        w[5]=b.x; w[6]=b.y; w[7]=b.z; w[8]=b.w;
        w[9]=c.x; w[10]=c.y; w[11]=c.z; w[12]=c.w;
        w[13]=d.x; w[14]=d.y; w[15]=d.z; w[16]=d.w;
        if (!rv) {
#pragma unroll
            for (int i = 0; i < 17; i++) w[i] = 0.f;
        }
    };

    auto applyW = [&](float (&w)[17], int ci, int ar, int ky) {
#pragma unroll
        for (int oc = 0; oc < TC; oc++) {
            const float4 wv = *(const float4*)(wsf + (ci * TC + oc) * 12 + ky * 4);
            if (ar == 0) {
#pragma unroll
                for (int j = 0; j < 8; j++) {
                    float a = acc[0][oc][j];
                    a = fmaf(w[j * 2 + 0], wv.x, a);
                    a = fmaf(w[j * 2 + 1], wv.y, a);
                    a = fmaf(w[j * 2 + 2], wv.z, a);
                    acc[0][oc][j] = a;
                }
            } else {
#pragma unroll
                for (int j = 0; j < 8; j++) {
                    float a = acc[1][oc][j];
                    a = fmaf(w[j * 2 + 0], wv.x, a);
                    a = fmaf(w[j * 2 + 1], wv.y, a);
                    a = fmaf(w[j * 2 + 2], wv.z, a);
                    acc[1][oc][j] = a;
                }
            }
        }
    };

    auto dispatch = [&](float (&w)[17], int ci, int t) {
        switch (t) {
            case 0: applyW(w, ci, 0, 0); break;
            case 1: applyW(w, ci, 0, 1); break;
            case 2: applyW(w, ci, 0, 2); applyW(w, ci, 1, 0); break;
            case 3: applyW(w, ci, 1, 1); break;
            default: applyW(w, ci, 1, 2); break;
        }
    };

    float bufA[17], bufB[17];
    for (int cc = 0; cc < Cin; cc += CICH) {
        const int chunk = min(CICH, Cin - cc);
        __syncthreads();
        for (int i = tid; i < chunk * TC * 9; i += nthr) {
            int ci = i / (TC * 9);
            int r  = i - ci * (TC * 9);
            int oc = r / 9;
            int k  = r - oc * 9;
            wsf[(ci * TC + oc) * 12 + (k / 3) * 4 + (k % 3)] =
                wgt[(size_t)(ocg + oc) * Cin * 9 + (size_t)(cc + ci) * 9 + k];
        }
        __syncthreads();
        const int total = chunk * 5;
        loadRowT(bufA, cc, 0);
        for (int m = 0; m < total; m++) {
            const int mn = m + 1;
            if (m & 1) {
                if (mn < total) loadRowT(bufA, cc + mn / 5, mn % 5);
                dispatch(bufB, m / 5, m % 5);
            } else {
                if (mn < total) loadRowT(bufB, cc + mn / 5, mn % 5);
                dispatch(bufA, m / 5, m % 5);
            }
        }
    }

#pragma unroll
    for (int ar = 0; ar < 2; ar++) {
#pragma unroll
        for (int oc = 0; oc < TC; oc++) {
            float bv = bias[ocg + oc];
            float* op = out + (((size_t)n * Cout + ocg + oc) * Hout + oy0 + ar) * Wout + ox0;
            float v[8];
#pragma unroll
            for (int j = 0; j < 8; j++) {
                float a = acc[ar][oc][j] + bv;
                if (ACT == 1) a = a > 0.f ? a : 0.f;
                v[j] = a;
            }
            *(float4*)(op)     = make_float4(v[0], v[1], v[2], v[3]);
            *(float4*)(op + 4) = make_float4(v[4], v[5], v[6], v[7]);
        }
    }
}

// ---------------- transposed conv k=3 s=2 p=1 op=1, scalar, TC=8 --------------
template<int ACT>
__global__ void __launch_bounds__(128) deconvS_k(
    const float* __restrict__ in, const float* __restrict__ wgt,  // [Cin][Cout][3][3]
    const float* __restrict__ bias, float* __restrict__ out,
    int Cin, int Cout, int Hin, int Win)
{
    constexpr int CICH = 32;
    constexpr int TC = 8;
    __shared__ float wsf[CICH * TC * 12];

    const int Hout = Hin * 2, Wout = Win * 2;
    const int tid  = threadIdx.x;
    const int W4   = Wout >> 2;
    const int rows = 128 / W4;
    const int q    = tid % W4;
    const int a    = blockIdx.y * rows + tid / W4;
    const int b    = q * 2;
    const int ocg  = blockIdx.x * TC;
    const int n    = blockIdx.z;

    const bool v_a1 = (a + 1) < Hin;
    const bool v_b2 = (b + 2) < Win;

    float acc[TC][8];
#pragma unroll
    for (int o = 0; o < TC; o++)
#pragma unroll
        for (int j = 0; j < 8; j++) acc[o][j] = 0.f;

    auto loadRaw = [&](float (&rw)[6], int cabs) {
        const float* ip = in + ((size_t)n * Cin + cabs) * Hin * Win;
        const float* r0 = ip + (size_t)a * Win + b;
        float2 p0 = *(const float2*)r0;
        rw[0] = p0.x; rw[1] = p0.y;
        rw[2] = v_b2 ? r0[2] : 0.f;
        if (v_a1) {
            const float* r1 = r0 + Win;
            float2 p1 = *(const float2*)r1;
            rw[3] = p1.x; rw[4] = p1.y; rw[5] = v_b2 ? r1[2] : 0.f;
        } else {
            rw[3] = 0.f; rw[4] = 0.f; rw[5] = 0.f;
        }
    };
    auto computeCi = [&](float (&rw)[6], int ci) {
        float i00 = rw[0], i01 = rw[1], i02 = rw[2];
        float i10 = rw[3], i11 = rw[4], i12 = rw[5];
#pragma unroll
        for (int oc = 0; oc < TC; oc++) {
            const float* wp = wsf + (ci * TC + oc) * 12;
            const float4 A = *(const float4*)(wp);
            const float4 B = *(const float4*)(wp + 4);
            const float w22 = wp[8];
            float w00=A.x, w01=A.y, w02=A.z, w10=A.w;
            float w11=B.x, w12=B.y, w20=B.z, w21=B.w;
            acc[oc][0] = fmaf(i00, w11, acc[oc][0]);
            acc[oc][1] = fmaf(i00, w12, fmaf(i01, w10, acc[oc][1]));
            acc[oc][2] = fmaf(i01, w11, acc[oc][2]);
            acc[oc][3] = fmaf(i01, w12, fmaf(i02, w10, acc[oc][3]));
            acc[oc][4] = fmaf(i00, w21, fmaf(i10, w01, acc[oc][4]));
            acc[oc][5] = fmaf(i00, w22, fmaf(i01, w20, fmaf(i10, w02, fmaf(i11, w00, acc[oc][5]))));
            acc[oc][6] = fmaf(i01, w21, fmaf(i11, w01, acc[oc][6]));
            acc[oc][7] = fmaf(i01, w22, fmaf(i02, w20, fmaf(i11, w02, fmaf(i12, w00, acc[oc][7]))));
        }
    };

    float rawA[6], rawB[6];
    for (int cc = 0; cc < Cin; cc += CICH) {
        const int chunk = min(CICH, Cin - cc);
        __syncthreads();
        for (int i = tid; i < chunk * TC * 9; i += 128) {
            int ci = i / (TC * 9);
            int r  = i - ci * (TC * 9);
            int oc = r / 9;
            int k  = r - oc * 9;
            wsf[(ci * TC + oc) * 12 + k] =
                wgt[(size_t)(cc + ci) * Cout * 9 + (size_t)(ocg + oc) * 9 + k];
        }
        __syncthreads();
        loadRaw(rawA, cc);
        for (int ci = 0; ci < chunk; ci += 2) {
            if (ci + 1 < chunk) loadRaw(rawB, cc + ci + 1);
            computeCi(rawA, ci);
            if (ci + 2 < chunk) loadRaw(rawA, cc + ci + 2);
            if (ci + 1 < chunk) computeCi(rawB, ci + 1);
        }
    }

#pragma unroll
    for (int oc = 0; oc < TC; oc++) {
        float bv = bias[ocg + oc];
        float* op = out + (((size_t)n * Cout + ocg + oc) * Hout + 2 * a) * Wout + 4 * q;
        float v0[4], v1[4];
#pragma unroll
        for (int j = 0; j < 4; j++) {
            float x0 = acc[oc][j] + bv;
            float x1 = acc[oc][4 + j] + bv;
            if (ACT == 1) { x0 = x0 > 0.f ? x0 : 0.f; x1 = x1 > 0.f ? x1 : 0.f; }
            v0[j] = x0; v1[j] = x1;
        }
        *(float4*)(op)        = make_float4(v0[0], v0[1], v0[2], v0[3]);
        *(float4*)(op + Wout) = make_float4(v1[0], v1[1], v1[2], v1[3]);
    }
}

// ---------------- scalar conv (final 3-channel sigmoid layer) -------------
template<int STRIDE, int TC, int ACT>
__global__ void __launch_bounds__(128) convS_k(
    const float* __restrict__ in, const float* __restrict__ wgt,
    const float* __restrict__ bias, float* __restrict__ out,
    int Cin, int Cout, int Hin, int Win, int Hout, int Wout)
{
    constexpr int CICH = 32;
    constexpr int NC = (STRIDE == 1) ? 6 : 9;
    __shared__ float ws[CICH * TC * 9];

    const int tid  = threadIdx.x;
    const int W4   = Wout >> 2;
    const int rows = 128 / W4;
    const int lane = tid % W4;
    const int row  = tid / W4;
    const int oy   = blockIdx.y * rows + row;
    const int ox0  = lane * 4;
    const int ocg  = blockIdx.x * TC;
    const int n    = blockIdx.z;

    float acc[TC][4];
#pragma unroll
    for (int a = 0; a < TC; a++)
#pragma unroll
        for (int j = 0; j < 4; j++) acc[a][j] = 0.f;

    bool cval[NC];
#pragma unroll
    for (int c = 0; c < NC; c++) {
        int ix = ox0 * STRIDE + c - 1;
        cval[c] = (ix >= 0 && ix < Win);
    }
    const int ixbase = ox0 * STRIDE - 1;
    bool rval[3]; int iyo[3];
#pragma unroll
    for (int ky = 0; ky < 3; ky++) {
        int iy = oy * STRIDE + ky - 1;
        rval[ky] = (iy >= 0 && iy < Hin);
        iyo[ky] = iy;
    }

    for (int cc = 0; cc < Cin; cc += CICH) {
        const int chunk = min(CICH, Cin - cc);
        __syncthreads();
        for (int i = tid; i < chunk * TC * 9; i += 128) {
            int ci = i / (TC * 9);
            int r  = i - ci * (TC * 9);
            int oc = r / 9;
            int k  = r - oc * 9;
            ws[i] = wgt[(size_t)(ocg + oc) * Cin * 9 + (size_t)(cc + ci) * 9 + k];
        }
        __syncthreads();
        for (int ci = 0; ci < chunk; ci++) {
            const float* ip = in + ((size_t)n * Cin + cc + ci) * Hin * Win;
            float iv[3][NC];
#pragma unroll
            for (int ky = 0; ky < 3; ky++) {
                const float* rp = ip + (long)iyo[ky] * Win + ixbase;
#pragma unroll
                for (int c = 0; c < NC; c++)
                    iv[ky][c] = (rval[ky] && cval[c]) ? rp[c] : 0.f;
            }
            const float* wp = ws + ci * TC * 9;
#pragma unroll
            for (int oc = 0; oc < TC; oc++) {
#pragma unroll
                for (int ky = 0; ky < 3; ky++)
#pragma unroll
                    for (int kx = 0; kx < 3; kx++) {
                        float wv = wp[oc * 9 + ky * 3 + kx];
#pragma unroll
                        for (int j = 0; j < 4; j++)
                            acc[oc][j] = fmaf(iv[ky][j * STRIDE + kx], wv, acc[oc][j]);
                    }
            }
        }
    }
#pragma unroll
    for (int oc = 0; oc < TC; oc++) {
        float bv = bias[ocg + oc];
        float* op = out + (((size_t)n * Cout + ocg + oc) * Hout + oy) * Wout + ox0;
#pragma unroll
        for (int j = 0; j < 4; j++) {
            float v = acc[oc][j] + bv;
            if (ACT == 1) v = v > 0.f ? v : 0.f;
            if (ACT == 2) v = 1.f / (1.f + expf(-v));
            op[j] = v;
        }
    }
}

// ---------------- z [B,512,32,32] -> zf [16384, 512] ----------------
__global__ void __launch_bounds__(256) zt_k(const float* __restrict__ z,
                                            float* __restrict__ zf)
{
    __shared__ float t[128 * 33];
    const int blk = blockIdx.x;
    const int bb  = blk >> 5;
    const int y   = blk & 31;
    const int tid = threadIdx.x;
    for (int cc = 0; cc < 512; cc += 128) {
        __syncthreads();
        for (int i = tid; i < 128 * 32; i += 256) {
            int c = i >> 5, x = i & 31;
            t[c * 33 + x] = z[(((size_t)bb * 512 + cc + c) * 32 + y) * 32 + x];
        }
        __syncthreads();
        for (int i = tid; i < 32 * 128; i += 256) {
            int x = i >> 7, c = i & 127;
            zf[((size_t)bb * 1024 + y * 32 + x) * 512 + cc + c] = t[c * 33 + x];
        }
    }
}

// ---------------- codebook row norms ----------------
__global__ void __launch_bounds__(256) cnorm_k(const float* __restrict__ cb,
                                               float* __restrict__ cn)
{
    const int warp = threadIdx.x >> 5, lane = threadIdx.x & 31;
    const int code = blockIdx.x * 8 + warp;
    const float* p = cb + (size_t)code * 512;
    float s = 0.f;
    for (int d = lane; d < 512; d += 32) { float v = p[d]; s = fmaf(v, v, s); }
#pragma unroll
    for (int o = 16; o > 0; o >>= 1) s += __shfl_xor_sync(0xffffffffu, s, o);
    if (lane == 0) cn[code] = s;
}

// ---------------- quantizer v2: 32 rows/block, thread = 8 rows x 8 codes ------
// smem: zs [32][520] row-major (66.6KB), cbt double-buffered [2][1024][20] (160KB)
#define ZPQ 520
#define CPQ 20
__global__ void __launch_bounds__(512) quant8_k(const float* __restrict__ zf,
                                                const float* __restrict__ cb,
                                                const float* __restrict__ cn,
                                                int* __restrict__ idx)
{
    extern __shared__ float sm[];
    float* zs  = sm;                 // 32*520
    float* cbt = sm + 32 * ZPQ;      // 2 * 1024*20
    const int tid = threadIdx.x;
    const int t   = tid & 127;       // code lane
    const int rg  = tid >> 7;        // row group 0..3
    const int r0  = blockIdx.x * 32;

    // stage z rows (row-major, float4)
    for (int i = tid; i < 32 * 128; i += 512) {
        int r = i >> 7, dq = i & 127;
        float4 v = *(const float4*)(zf + (size_t)(r0 + r) * 512 + dq * 4);
        *(float4*)(zs + r * ZPQ + dq * 4) = v;
    }

    float best[8]; int bi[8];
#pragma unroll
    for (int r = 0; r < 8; r++) { best[r] = 3.4e38f; bi[r] = 0; }

    auto stage = [&](int cbase, int dch, int buf) {
        float* dst = cbt + buf * (1024 * CPQ);
        for (int i = tid; i < 4096; i += 512) {
            int c = i >> 2, dq = i & 3;
            float4 v = *(const float4*)(cb + (size_t)(cbase + c) * 512 + dch * 16 + dq * 4);
            *(float4*)(dst + c * CPQ + dq * 4) = v;
        }
    };

    for (int ct = 0; ct < 8; ct++) {
        const int cbase = ct * 1024;
        float acc[8][8];
#pragma unroll
        for (int rr = 0; rr < 8; rr++)
#pragma unroll
            for (int k = 0; k < 8; k++) acc[rr][k] = 0.f;

        __syncthreads();
        stage(cbase, 0, 0);
        for (int dch = 0; dch < 32; dch++) {
            __syncthreads();
            if (dch + 1 < 32) stage(cbase, dch + 1, (dch + 1) & 1);
            const float* cbuf = cbt + (dch & 1) * (1024 * CPQ);
#pragma unroll
            for (int dq = 0; dq < 4; dq++) {
                float4 zv[8];
#pragma unroll
                for (int rr = 0; rr < 8; rr++)
                    zv[rr] = *(const float4*)(zs + (rg * 8 + rr) * ZPQ + dch * 16 + dq * 4);
#pragma unroll
                for (int k = 0; k < 8; k++) {
                    float4 cv = *(const float4*)(cbuf + (k * 128 + t) * CPQ + dq * 4);
#pragma unroll
                    for (int rr = 0; rr < 8; rr++) {
                        float a = acc[rr][k];
                        a = fmaf(zv[rr].x, cv.x, a);
                        a = fmaf(zv[rr].y, cv.y, a);
                        a = fmaf(zv[rr].z, cv.z, a);
                        a = fmaf(zv[rr].w, cv.w, a);
                        acc[rr][k] = a;
                    }
                }
            }
        }
#pragma unroll
        for (int k = 0; k < 8; k++) {
            int cand = cbase + k * 128 + t;
            float nv = cn[cand];
#pragma unroll
            for (int rr = 0; rr < 8; rr++) {
                float s = nv - 2.f * acc[rr][k];
                if (s < best[rr]) { best[rr] = s; bi[rr] = cand; }
            }
        }
    }

    // reduction: 4 independent 128-lane groups (rows rg*8 + rr)
    float* sv = sm;
    int*   si = (int*)(sm + 512);
    for (int rr = 0; rr < 8; rr++) {
        __syncthreads();
        sv[tid] = best[rr]; si[tid] = bi[rr];
        __syncthreads();
        for (int s = 64; s > 0; s >>= 1) {
            if (t < s) {
                float ov = sv[tid + s]; int oi = si[tid + s];
                if (ov < sv[tid] || (ov == sv[tid] && oi < si[tid])) { sv[tid] = ov; si[tid] = oi; }
            }
            __syncthreads();
        }
        if (t == 0) idx[r0 + rg * 8 + rr] = si[tid];
    }
}

// ---------------- zq gather ----------------
__global__ void __launch_bounds__(256) zqg_k(const float* __restrict__ cb,
                                             const int* __restrict__ idx,
                                             float* __restrict__ zq)
{
    size_t i = (size_t)blockIdx.x * 256 + threadIdx.x;
    if (i >= (size_t)NB * 512 * 32 * 32) return;
    int x = (int)(i & 31);
    int y = (int)((i >> 5) & 31);
    int c = (int)((i >> 10) & 511);
    int bb = (int)(i >> 19);
    int n = bb * 1024 + y * 32 + x;
    zq[i] = cb[(size_t)idx[n] * 512 + c];
}

// ---------------- indices -> tail of output ----------------
__global__ void __launch_bounds__(256) idxout_k(const int* __restrict__ idx,
                                                float* __restrict__ out,
                                                long out_off, long out_size)
{
    int i = blockIdx.x * 256 + threadIdx.x;
    if (i < 16384 && out_off + i < out_size) out[out_off + i] = (float)idx[i];
}

// ---------------- host launcher ----------------
extern "C" void kernel_launch(void* const* d_in, const int* in_sizes, int n_in,
                              void* d_out, int out_size)
{
    const float* x  = (const float*)d_in[0];
    const float* w1 = (const float*)d_in[1];  const float* b1 = (const float*)d_in[2];
    const float* w2 = (const float*)d_in[3];  const float* b2 = (const float*)d_in[4];
    const float* w3 = (const float*)d_in[5];  const float* b3 = (const float*)d_in[6];
    const float* w4 = (const float*)d_in[7];  const float* b4 = (const float*)d_in[8];
    const float* cb = (const float*)d_in[9];
    const float* d1w = (const float*)d_in[10]; const float* d1b = (const float*)d_in[11];
    const float* d2w = (const float*)d_in[12]; const float* d2b = (const float*)d_in[13];
    const float* d3w = (const float*)d_in[14]; const float* d3b = (const float*)d_in[15];
    const float* wo = (const float*)d_in[16]; const float* bo = (const float*)d_in[17];
    float* out = (float*)d_out;

    float *h1, *h2, *h3, *z, *zf, *zq, *g1, *g2, *g3, *cn;
    int* idx;
    cudaGetSymbolAddress((void**)&h1, g_h1);
    cudaGetSymbolAddress((void**)&h2, g_h2);
    cudaGetSymbolAddress((void**)&h3, g_h3);
    cudaGetSymbolAddress((void**)&z,  g_z);
    cudaGetSymbolAddress((void**)&zf, g_zf);
    cudaGetSymbolAddress((void**)&zq, g_zq);
    cudaGetSymbolAddress((void**)&g1, g_g1);
    cudaGetSymbolAddress((void**)&g2, g_g2);
    cudaGetSymbolAddress((void**)&g3, g_g3);
    cudaGetSymbolAddress((void**)&cn, g_cn);
    cudaGetSymbolAddress((void**)&idx, g_idx);

    // Encoder
    conv8s_k<1, 1><<<dim3(8, 64, NB), 128>>>(x, w1, b1, h1, 3, 64, 256, 256, 256, 256);
    // stride-2 convs: 2-row vertical blocking, TC=4
    convV_k<1><<<dim3(32, 8, NB), 128>>>(h1, w2, b2, h2,  64, 128, 256, 256, 128, 128);
    convV_k<1><<<dim3(64, 2, NB), 128>>>(h2, w3, b3, h3, 128, 256, 128, 128,  64,  64);
    convV_k<0><<<dim3(128, 1, NB), 64>>>(h3, w4, b4, z,  256, 512,  64,  64,  32,  32);

    // Quantize
    zt_k<<<512, 256>>>(z, zf);
    cnorm_k<<<1024, 256>>>(cb, cn);
    const int qsmem = (32 * ZPQ + 2 * 1024 * CPQ) * 4;  // 66560 + 163840 = 230400 B
    cudaFuncSetAttribute(quant8_k, cudaFuncAttributeMaxDynamicSharedMemorySize, qsmem);
    quant8_k<<<512, 512, qsmem>>>(zf, cb, cn, idx);
    zqg_k<<<(NB * 512 * 32 * 32 + 255) / 256, 256>>>(cb, idx, zq);

    // Decoder
    deconvS_k<1><<<dim3(32,  4, NB), 128>>>(zq, d1w, d1b, g1, 512, 256,  32,  32);
    deconvS_k<1><<<dim3(16, 16, NB), 128>>>(g1, d2w, d2b, g2, 256, 128,  64,  64);
    deconvS_k<1><<<dim3( 8, 64, NB), 128>>>(g2, d3w, d3b, g3, 128,  64, 128, 128);
    convS_k<1, 3, 2><<<dim3(1, 128, NB), 128>>>(g3, wo, bo, out, 64, 3, 256, 256, 256, 256);

    // Indices appended after reconstruction
    idxout_k<<<64, 256>>>(idx, out, (long)NB * 3 * 256 * 256, (long)out_size);
}

// round 6
// speedup vs baseline: 1.1752x; 1.1752x over previous
#include <cuda_runtime.h>
#include <math.h>

// ---------------- scratch (device globals; no allocations) ----------------
#define NB 16
__device__ float g_h1[NB*64*256*256];
__device__ float g_h2[NB*128*128*128];
__device__ float g_h3[NB*256*64*64];
__device__ float g_z [NB*512*32*32];
__device__ float g_zf[NB*1024*512];
__device__ float g_zq[NB*512*32*32];
__device__ float g_g1[NB*256*64*64];
__device__ float g_g2[NB*128*128*128];
__device__ float g_g3[NB*64*256*256];
__device__ float g_cn[8192];
__device__ int   g_idx[16384];

// ---------------- 3x3 conv, pad=1, 8-wide, TC output channels ----------------
// Thread: 8 horizontal outputs x TC output channels. Coalesced float4 loads,
// halo via shfl. Weights smem [ci][oc][ky][4] -> one LDS.128 per (oc,row).
// ACT: 0 none, 1 relu, 2 sigmoid
template<int STRIDE, int TC, int ACT>
__global__ void __launch_bounds__(128) conv8s_k(
    const float* __restrict__ in, const float* __restrict__ wgt,
    const float* __restrict__ bias, float* __restrict__ out,
    int Cin, int Cout, int Hin, int Win, int Hout, int Wout)
{
    constexpr int CICH = 32;
    constexpr int NW = (STRIDE == 1) ? 10 : 17;
    __shared__ float wsf[CICH * TC * 12];

    const int tid  = threadIdx.x;
    const int W8   = Wout >> 3;
    const int rows = 128 / W8;
    const int q    = tid % W8;
    const int oy   = blockIdx.y * rows + tid / W8;
    const int ox0  = q * 8;
    const int ocg  = blockIdx.x * TC;
    const int n    = blockIdx.z;

    float acc[TC][8];
#pragma unroll
    for (int o = 0; o < TC; o++)
#pragma unroll
        for (int j = 0; j < 8; j++) acc[o][j] = 0.f;

    bool rval[3]; int iyo[3];
#pragma unroll
    for (int ky = 0; ky < 3; ky++) {
        int iy = oy * STRIDE + ky - 1;
        rval[ky] = (iy >= 0 && iy < Hin);
        iyo[ky] = iy < 0 ? 0 : (iy >= Hin ? Hin - 1 : iy);
    }

    auto loadRow = [&](float (&w)[NW], int cabs, int ky) {
        const float* rp = in + ((size_t)(n * Cin + cabs) * Hin + iyo[ky]) * Win;
        if (STRIDE == 1) {
            float4 a = *(const float4*)(rp + ox0);
            float4 b = *(const float4*)(rp + ox0 + 4);
            float lft = __shfl_up_sync(0xffffffffu, b.w, 1);
            float rgt = __shfl_down_sync(0xffffffffu, a.x, 1);
            if (q == 0) lft = 0.f;
            if (q == W8 - 1) rgt = 0.f;
            w[0]=lft; w[1]=a.x; w[2]=a.y; w[3]=a.z; w[4]=a.w;
            w[5]=b.x; w[6]=b.y; w[7]=b.z; w[8]=b.w; w[9]=rgt;
        } else {
            const int ib = ox0 * 2;
            float4 a = *(const float4*)(rp + ib);
            float4 b = *(const float4*)(rp + ib + 4);
            float4 c = *(const float4*)(rp + ib + 8);
            float4 d = *(const float4*)(rp + ib + 12);
            float lft = __shfl_up_sync(0xffffffffu, d.w, 1);
            if (q == 0) lft = 0.f;
            w[0]=lft;
            w[1]=a.x; w[2]=a.y; w[3]=a.z; w[4]=a.w;
            w[5]=b.x; w[6]=b.y; w[7]=b.z; w[8]=b.w;
            w[9]=c.x; w[10]=c.y; w[11]=c.z; w[12]=c.w;
            w[13]=d.x; w[14]=d.y; w[15]=d.z; w[16]=d.w;
        }
        if (!rval[ky]) {
#pragma unroll
            for (int i = 0; i < NW; i++) w[i] = 0.f;
        }
    };

    auto computeRow = [&](float (&w)[NW], int ci, int ky) {
#pragma unroll
        for (int oc = 0; oc < TC; oc++) {
            const float4 wv = *(const float4*)(wsf + (ci * TC + oc) * 12 + ky * 4);
#pragma unroll
            for (int j = 0; j < 8; j++) {
                float a = acc[oc][j];
                a = fmaf(w[j * STRIDE + 0], wv.x, a);
                a = fmaf(w[j * STRIDE + 1], wv.y, a);
                a = fmaf(w[j * STRIDE + 2], wv.z, a);
                acc[oc][j] = a;
            }
        }
    };

    float bufA[NW], bufB[NW];
    for (int cc = 0; cc < Cin; cc += CICH) {
        const int chunk = min(CICH, Cin - cc);
        __syncthreads();
        for (int i = tid; i < chunk * TC * 9; i += 128) {
            int ci = i / (TC * 9);
            int r  = i - ci * (TC * 9);
            int oc = r / 9;
            int k  = r - oc * 9;
            wsf[(ci * TC + oc) * 12 + (k / 3) * 4 + (k % 3)] =
                wgt[(size_t)(ocg + oc) * Cin * 9 + (size_t)(cc + ci) * 9 + k];
        }
        __syncthreads();
        const int total = chunk * 3;
        loadRow(bufA, cc, 0);
        for (int m = 0; m < total; m++) {
            const int mn = m + 1;
            if (m & 1) {
                if (mn < total) loadRow(bufA, cc + mn / 3, mn % 3);
                computeRow(bufB, m / 3, m % 3);
            } else {
                if (mn < total) loadRow(bufB, cc + mn / 3, mn % 3);
                computeRow(bufA, m / 3, m % 3);
            }
        }
    }

#pragma unroll
    for (int oc = 0; oc < TC; oc++) {
        float bv = bias[ocg + oc];
        float* op = out + (((size_t)n * Cout + ocg + oc) * Hout + oy) * Wout + ox0;
        float v[8];
#pragma unroll
        for (int j = 0; j < 8; j++) {
            float a = acc[oc][j] + bv;
            if (ACT == 1) a = a > 0.f ? a : 0.f;
            if (ACT == 2) a = 1.f / (1.f + expf(-a));
            v[j] = a;
        }
        *(float4*)(op)     = make_float4(v[0], v[1], v[2], v[3]);
        *(float4*)(op + 4) = make_float4(v[4], v[5], v[6], v[7]);
    }
}

// ---------------- transposed conv k=3 s=2 p=1 op=1, scalar, TC=8 --------------
template<int ACT>
__global__ void __launch_bounds__(128) deconvS_k(
    const float* __restrict__ in, const float* __restrict__ wgt,  // [Cin][Cout][3][3]
    const float* __restrict__ bias, float* __restrict__ out,
    int Cin, int Cout, int Hin, int Win)
{
    constexpr int CICH = 32;
    constexpr int TC = 8;
    __shared__ float wsf[CICH * TC * 12];

    const int Hout = Hin * 2, Wout = Win * 2;
    const int tid  = threadIdx.x;
    const int W4   = Wout >> 2;
    const int rows = 128 / W4;
    const int q    = tid % W4;
    const int a    = blockIdx.y * rows + tid / W4;
    const int b    = q * 2;
    const int ocg  = blockIdx.x * TC;
    const int n    = blockIdx.z;

    const bool v_a1 = (a + 1) < Hin;
    const bool v_b2 = (b + 2) < Win;

    float acc[TC][8];
#pragma unroll
    for (int o = 0; o < TC; o++)
#pragma unroll
        for (int j = 0; j < 8; j++) acc[o][j] = 0.f;

    auto loadRaw = [&](float (&rw)[6], int cabs) {
        const float* ip = in + ((size_t)n * Cin + cabs) * Hin * Win;
        const float* r0 = ip + (size_t)a * Win + b;
        float2 p0 = *(const float2*)r0;
        rw[0] = p0.x; rw[1] = p0.y;
        rw[2] = v_b2 ? r0[2] : 0.f;
        if (v_a1) {
            const float* r1 = r0 + Win;
            float2 p1 = *(const float2*)r1;
            rw[3] = p1.x; rw[4] = p1.y; rw[5] = v_b2 ? r1[2] : 0.f;
        } else {
            rw[3] = 0.f; rw[4] = 0.f; rw[5] = 0.f;
        }
    };
    auto computeCi = [&](float (&rw)[6], int ci) {
        float i00 = rw[0], i01 = rw[1], i02 = rw[2];
        float i10 = rw[3], i11 = rw[4], i12 = rw[5];
#pragma unroll
        for (int oc = 0; oc < TC; oc++) {
            const float* wp = wsf + (ci * TC + oc) * 12;
            const float4 A = *(const float4*)(wp);
            const float4 B = *(const float4*)(wp + 4);
            const float w22 = wp[8];
            float w00=A.x, w01=A.y, w02=A.z, w10=A.w;
            float w11=B.x, w12=B.y, w20=B.z, w21=B.w;
            acc[oc][0] = fmaf(i00, w11, acc[oc][0]);
            acc[oc][1] = fmaf(i00, w12, fmaf(i01, w10, acc[oc][1]));
            acc[oc][2] = fmaf(i01, w11, acc[oc][2]);
            acc[oc][3] = fmaf(i01, w12, fmaf(i02, w10, acc[oc][3]));
            acc[oc][4] = fmaf(i00, w21, fmaf(i10, w01, acc[oc][4]));
            acc[oc][5] = fmaf(i00, w22, fmaf(i01, w20, fmaf(i10, w02, fmaf(i11, w00, acc[oc][5]))));
            acc[oc][6] = fmaf(i01, w21, fmaf(i11, w01, acc[oc][6]));
            acc[oc][7] = fmaf(i01, w22, fmaf(i02, w20, fmaf(i11, w02, fmaf(i12, w00, acc[oc][7]))));
        }
    };

    float rawA[6], rawB[6];
    for (int cc = 0; cc < Cin; cc += CICH) {
        const int chunk = min(CICH, Cin - cc);
        __syncthreads();
        for (int i = tid; i < chunk * TC * 9; i += 128) {
            int ci = i / (TC * 9);
            int r  = i - ci * (TC * 9);
            int oc = r / 9;
            int k  = r - oc * 9;
            wsf[(ci * TC + oc) * 12 + k] =
                wgt[(size_t)(cc + ci) * Cout * 9 + (size_t)(ocg + oc) * 9 + k];
        }
        __syncthreads();
        loadRaw(rawA, cc);
        for (int ci = 0; ci < chunk; ci += 2) {
            if (ci + 1 < chunk) loadRaw(rawB, cc + ci + 1);
            computeCi(rawA, ci);
            if (ci + 2 < chunk) loadRaw(rawA, cc + ci + 2);
            if (ci + 1 < chunk) computeCi(rawB, ci + 1);
        }
    }

#pragma unroll
    for (int oc = 0; oc < TC; oc++) {
        float bv = bias[ocg + oc];
        float* op = out + (((size_t)n * Cout + ocg + oc) * Hout + 2 * a) * Wout + 4 * q;
        float v0[4], v1[4];
#pragma unroll
        for (int j = 0; j < 4; j++) {
            float x0 = acc[oc][j] + bv;
            float x1 = acc[oc][4 + j] + bv;
            if (ACT == 1) { x0 = x0 > 0.f ? x0 : 0.f; x1 = x1 > 0.f ? x1 : 0.f; }
            v0[j] = x0; v1[j] = x1;
        }
        *(float4*)(op)        = make_float4(v0[0], v0[1], v0[2], v0[3]);
        *(float4*)(op + Wout) = make_float4(v1[0], v1[1], v1[2], v1[3]);
    }
}

// ---------------- z [B,512,32,32] -> zf [16384, 512] ----------------
__global__ void __launch_bounds__(256) zt_k(const float* __restrict__ z,
                                            float* __restrict__ zf)
{
    __shared__ float t[128 * 33];
    const int blk = blockIdx.x;
    const int bb  = blk >> 5;
    const int y   = blk & 31;
    const int tid = threadIdx.x;
    for (int cc = 0; cc < 512; cc += 128) {
        __syncthreads();
        for (int i = tid; i < 128 * 32; i += 256) {
            int c = i >> 5, x = i & 31;
            t[c * 33 + x] = z[(((size_t)bb * 512 + cc + c) * 32 + y) * 32 + x];
        }
        __syncthreads();
        for (int i = tid; i < 32 * 128; i += 256) {
            int x = i >> 7, c = i & 127;
            zf[((size_t)bb * 1024 + y * 32 + x) * 512 + cc + c] = t[c * 33 + x];
        }
    }
}

// ---------------- codebook row norms ----------------
__global__ void __launch_bounds__(256) cnorm_k(const float* __restrict__ cb,
                                               float* __restrict__ cn)
{
    const int warp = threadIdx.x >> 5, lane = threadIdx.x & 31;
    const int code = blockIdx.x * 8 + warp;
    const float* p = cb + (size_t)code * 512;
    float s = 0.f;
    for (int d = lane; d < 512; d += 32) { float v = p[d]; s = fmaf(v, v, s); }
#pragma unroll
    for (int o = 16; o > 0; o >>= 1) s += __shfl_xor_sync(0xffffffffu, s, o);
    if (lane == 0) cn[code] = s;
}

// ---------------- quantizer: 32 rows/block, thread = 8 rows x 8 codes ---------
// smem: zs [32][520] row-major (66.6KB), cbt double-buffered [2][1024][20] (160KB)
#define ZPQ 520
#define CPQ 20
__global__ void __launch_bounds__(512) quant8_k(const float* __restrict__ zf,
                                                const float* __restrict__ cb,
                                                const float* __restrict__ cn,
                                                int* __restrict__ idx)
{
    extern __shared__ float sm[];
    float* zs  = sm;                 // 32*520
    float* cbt = sm + 32 * ZPQ;      // 2 * 1024*20
    const int tid = threadIdx.x;
    const int t   = tid & 127;       // code lane
    const int rg  = tid >> 7;        // row group 0..3
    const int r0  = blockIdx.x * 32;

    for (int i = tid; i < 32 * 128; i += 512) {
        int r = i >> 7, dq = i & 127;
        float4 v = *(const float4*)(zf + (size_t)(r0 + r) * 512 + dq * 4);
        *(float4*)(zs + r * ZPQ + dq * 4) = v;
    }

    float best[8]; int bi[8];
#pragma unroll
    for (int r = 0; r < 8; r++) { best[r] = 3.4e38f; bi[r] = 0; }

    auto stage = [&](int cbase, int dch, int buf) {
        float* dst = cbt + buf * (1024 * CPQ);
        for (int i = tid; i < 4096; i += 512) {
            int c = i >> 2, dq = i & 3;
            float4 v = *(const float4*)(cb + (size_t)(cbase + c) * 512 + dch * 16 + dq * 4);
            *(float4*)(dst + c * CPQ + dq * 4) = v;
        }
    };

    for (int ct = 0; ct < 8; ct++) {
        const int cbase = ct * 1024;
        float acc[8][8];
#pragma unroll
        for (int rr = 0; rr < 8; rr++)
#pragma unroll
            for (int k = 0; k < 8; k++) acc[rr][k] = 0.f;

        __syncthreads();
        stage(cbase, 0, 0);
        for (int dch = 0; dch < 32; dch++) {
            __syncthreads();
            if (dch + 1 < 32) stage(cbase, dch + 1, (dch + 1) & 1);
            const float* cbuf = cbt + (dch & 1) * (1024 * CPQ);
#pragma unroll
            for (int dq = 0; dq < 4; dq++) {
                float4 zv[8];
#pragma unroll
                for (int rr = 0; rr < 8; rr++)
                    zv[rr] = *(const float4*)(zs + (rg * 8 + rr) * ZPQ + dch * 16 + dq * 4);
#pragma unroll
                for (int k = 0; k < 8; k++) {
                    float4 cv = *(const float4*)(cbuf + (k * 128 + t) * CPQ + dq * 4);
#pragma unroll
                    for (int rr = 0; rr < 8; rr++) {
                        float a = acc[rr][k];
                        a = fmaf(zv[rr].x, cv.x, a);
                        a = fmaf(zv[rr].y, cv.y, a);
                        a = fmaf(zv[rr].z, cv.z, a);
                        a = fmaf(zv[rr].w, cv.w, a);
                        acc[rr][k] = a;
                    }
                }
            }
        }
#pragma unroll
        for (int k = 0; k < 8; k++) {
            int cand = cbase + k * 128 + t;
            float nv = cn[cand];
#pragma unroll
            for (int rr = 0; rr < 8; rr++) {
                float s = nv - 2.f * acc[rr][k];
                if (s < best[rr]) { best[rr] = s; bi[rr] = cand; }
            }
        }
    }

    float* sv = sm;
    int*   si = (int*)(sm + 512);
    for (int rr = 0; rr < 8; rr++) {
        __syncthreads();
        sv[tid] = best[rr]; si[tid] = bi[rr];
        __syncthreads();
        for (int s = 64; s > 0; s >>= 1) {
            if (t < s) {
                float ov = sv[tid + s]; int oi = si[tid + s];
                if (ov < sv[tid] || (ov == sv[tid] && oi < si[tid])) { sv[tid] = ov; si[tid] = oi; }
            }
            __syncthreads();
        }
        if (t == 0) idx[r0 + rg * 8 + rr] = si[tid];
    }
}

// ---------------- zq gather ----------------
__global__ void __launch_bounds__(256) zqg_k(const float* __restrict__ cb,
                                             const int* __restrict__ idx,
                                             float* __restrict__ zq)
{
    size_t i = (size_t)blockIdx.x * 256 + threadIdx.x;
    if (i >= (size_t)NB * 512 * 32 * 32) return;
    int x = (int)(i & 31);
    int y = (int)((i >> 5) & 31);
    int c = (int)((i >> 10) & 511);
    int bb = (int)(i >> 19);
    int n = bb * 1024 + y * 32 + x;
    zq[i] = cb[(size_t)idx[n] * 512 + c];
}

// ---------------- indices -> tail of output ----------------
__global__ void __launch_bounds__(256) idxout_k(const int* __restrict__ idx,
                                                float* __restrict__ out,
                                                long out_off, long out_size)
{
    int i = blockIdx.x * 256 + threadIdx.x;
    if (i < 16384 && out_off + i < out_size) out[out_off + i] = (float)idx[i];
}

// ---------------- host launcher ----------------
extern "C" void kernel_launch(void* const* d_in, const int* in_sizes, int n_in,
                              void* d_out, int out_size)
{
    const float* x  = (const float*)d_in[0];
    const float* w1 = (const float*)d_in[1];  const float* b1 = (const float*)d_in[2];
    const float* w2 = (const float*)d_in[3];  const float* b2 = (const float*)d_in[4];
    const float* w3 = (const float*)d_in[5];  const float* b3 = (const float*)d_in[6];
    const float* w4 = (const float*)d_in[7];  const float* b4 = (const float*)d_in[8];
    const float* cb = (const float*)d_in[9];
    const float* d1w = (const float*)d_in[10]; const float* d1b = (const float*)d_in[11];
    const float* d2w = (const float*)d_in[12]; const float* d2b = (const float*)d_in[13];
    const float* d3w = (const float*)d_in[14]; const float* d3b = (const float*)d_in[15];
    const float* wo = (const float*)d_in[16]; const float* bo = (const float*)d_in[17];
    float* out = (float*)d_out;

    float *h1, *h2, *h3, *z, *zf, *zq, *g1, *g2, *g3, *cn;
    int* idx;
    cudaGetSymbolAddress((void**)&h1, g_h1);
    cudaGetSymbolAddress((void**)&h2, g_h2);
    cudaGetSymbolAddress((void**)&h3, g_h3);
    cudaGetSymbolAddress((void**)&z,  g_z);
    cudaGetSymbolAddress((void**)&zf, g_zf);
    cudaGetSymbolAddress((void**)&zq, g_zq);
    cudaGetSymbolAddress((void**)&g1, g_g1);
    cudaGetSymbolAddress((void**)&g2, g_g2);
    cudaGetSymbolAddress((void**)&g3, g_g3);
    cudaGetSymbolAddress((void**)&cn, g_cn);
    cudaGetSymbolAddress((void**)&idx, g_idx);

    // codebook norms first (independent)
    cnorm_k<<<1024, 256>>>(cb, cn);

    // Encoder (R4-proven conv8s, TC=8)
    conv8s_k<1, 8, 1><<<dim3( 8, 64, NB), 128>>>(x,  w1, b1, h1,   3,  64, 256, 256, 256, 256);
    conv8s_k<2, 8, 1><<<dim3(16, 16, NB), 128>>>(h1, w2, b2, h2,  64, 128, 256, 256, 128, 128);
    conv8s_k<2, 8, 1><<<dim3(32,  4, NB), 128>>>(h2, w3, b3, h3, 128, 256, 128, 128,  64,  64);
    conv8s_k<2, 8, 0><<<dim3(64,  1, NB), 128>>>(h3, w4, b4, z,  256, 512,  64,  64,  32,  32);

    // Quantize
    zt_k<<<512, 256>>>(z, zf);
    const int qsmem = (32 * ZPQ + 2 * 1024 * CPQ) * 4;  // 230400 B
    cudaFuncSetAttribute(quant8_k, cudaFuncAttributeMaxDynamicSharedMemorySize, qsmem);
    quant8_k<<<512, 512, qsmem>>>(zf, cb, cn, idx);
    zqg_k<<<(NB * 512 * 32 * 32 + 255) / 256, 256>>>(cb, idx, zq);

    // Decoder
    deconvS_k<1><<<dim3(32,  4, NB), 128>>>(zq, d1w, d1b, g1, 512, 256,  32,  32);
    deconvS_k<1><<<dim3(16, 16, NB), 128>>>(g1, d2w, d2b, g2, 256, 128,  64,  64);
    deconvS_k<1><<<dim3( 8, 64, NB), 128>>>(g2, d3w, d3b, g3, 128,  64, 128, 128);
    // Final sigmoid conv: 8-wide, TC=3
    conv8s_k<1, 3, 2><<<dim3(1, 64, NB), 128>>>(g3, wo, bo, out, 64, 3, 256, 256, 256, 256);

    // Indices appended after reconstruction
    idxout_k<<<64, 256>>>(idx, out, (long)NB * 3 * 256 * 256, (long)out_size);
}